// round 13
// baseline (speedup 1.0000x reference)
#include <cuda_runtime.h>
#include <cuda_fp16.h>
#include <cstdint>

#define T_LEN 16384
#define HID   512
#define NCHUNK 512
#define CHUNK_L 32
#define SA 40          // smem row stride in halves (32 used + 8 pad)

// ---------------------------------------------------------------------------
// Device scratch (no runtime allocation allowed)
// ---------------------------------------------------------------------------
__device__ __half g_xh[T_LEN * HID];
__device__ __half g_wz[HID * HID], g_wh[HID * HID], g_wo[HID * HID];
__device__ float2 g_ab[T_LEN * HID];      // (a, b) interleaved
__device__ __half g_sh[T_LEN * HID];
__device__ float2 g_agg[NCHUNK * HID];    // (A, B) per chunk
__device__ float g_pref[NCHUNK * HID];

// ---------------------------------------------------------------------------
// PTX helpers (sm_80-era: valid under compute_103 virtual arch)
// ---------------------------------------------------------------------------
__device__ __forceinline__ uint32_t smem_u32(const void* p) {
    uint32_t a;
    asm("{ .reg .u64 t; cvta.to.shared.u64 t, %1; cvt.u32.u64 %0, t; }" : "=r"(a) : "l"(p));
    return a;
}

__device__ __forceinline__ void cp16(uint32_t dst, const void* src) {
    asm volatile("cp.async.ca.shared.global [%0], [%1], 16;" :: "r"(dst), "l"(src));
}
#define CP_COMMIT() asm volatile("cp.async.commit_group;" ::: "memory")
#define CP_WAIT1()  asm volatile("cp.async.wait_group 1;" ::: "memory")

__device__ __forceinline__ void ldm4(uint32_t* r, uint32_t addr) {
    asm volatile("ldmatrix.sync.aligned.m8n8.x4.shared.b16 {%0,%1,%2,%3}, [%4];"
                 : "=r"(r[0]), "=r"(r[1]), "=r"(r[2]), "=r"(r[3]) : "r"(addr));
}

__device__ __forceinline__ void mma16816(float* d, const uint32_t* a, uint32_t b0, uint32_t b1) {
    asm volatile(
        "mma.sync.aligned.m16n8k16.row.col.f32.f16.f16.f32 "
        "{%0,%1,%2,%3}, {%4,%5,%6,%7}, {%8,%9}, {%0,%1,%2,%3};"
        : "+f"(d[0]), "+f"(d[1]), "+f"(d[2]), "+f"(d[3])
        : "r"(a[0]), "r"(a[1]), "r"(a[2]), "r"(a[3]), "r"(b0), "r"(b1));
}

// ---------------------------------------------------------------------------
// Fused fp32 -> fp16 converter: X then Wz, Wh, Wo, one launch.
// ---------------------------------------------------------------------------
#define NX2 (T_LEN * HID / 2)
#define NW2 (HID * HID / 2)

__global__ __launch_bounds__(256) void convert_all(const float* __restrict__ xs,
                                                   const float* __restrict__ Wz,
                                                   const float* __restrict__ Wh,
                                                   const float* __restrict__ Wo) {
    int i = blockIdx.x * 256 + threadIdx.x;
    const float* src;
    __half* dst;
    int j;
    if (i < NX2)                 { src = xs; dst = g_xh; j = i; }
    else if (i < NX2 + NW2)      { src = Wz; dst = g_wz; j = i - NX2; }
    else if (i < NX2 + 2 * NW2)  { src = Wh; dst = g_wh; j = i - NX2 - NW2; }
    else if (i < NX2 + 3 * NW2)  { src = Wo; dst = g_wo; j = i - NX2 - 2 * NW2; }
    else return;
    float2 x = *(const float2*)(src + j * 2);
    *(__half2*)(dst + j * 2) = __halves2half2(__float2half(x.x), __float2half(x.y));
}

// ---------------------------------------------------------------------------
// GEMM1: Z = X Wz^T + bz, Hc = X Wh^T + bh -> g_ab = (1-sig(Z), sig(Z)*Hc)
// BM=128 BN=64 BK=32, 16 chunks, 3-stage cp.async.
// Epilogue ALSO emits the per-chunk scan aggregates via warp shuffles:
// with CHUNK_L=32, warp wm's 32 rows are exactly chunk (blockIdx.y*4 + wm).
// ---------------------------------------------------------------------------
#define G1_STG 20480
#define G1_BZ 10240
#define G1_BH 15360

__device__ __forceinline__ void g1_load(int chunk, int st, int m0, int n0, int tid,
                                        uint32_t s) {
    const int k0 = chunk << 5;
    const uint32_t base = s + st * G1_STG;
    #pragma unroll
    for (int j = 0; j < 2; j++) {
        const int ch = tid + j * 256, row = ch >> 2, c = ch & 3;
        cp16(base + (row * SA + c * 8) * 2,
             g_xh + (size_t)(m0 + row) * HID + k0 + c * 8);
    }
    const int row = tid >> 2, c = tid & 3;
    const uint32_t off = (row * SA + c * 8) * 2;
    const size_t gsrc = (size_t)(n0 + row) * HID + k0 + c * 8;
    cp16(base + G1_BZ + off, g_wz + gsrc);
    cp16(base + G1_BH + off, g_wh + gsrc);
}

__global__ __launch_bounds__(256) void gemm1_kernel(const float* __restrict__ bz,
                                                    const float* __restrict__ bh) {
    extern __shared__ __half S1[];
    const int tid = threadIdx.x, wid = tid >> 5, l = tid & 31;
    const int wm = wid & 3, wn = wid >> 2;
    const int m0 = blockIdx.y * 128, n0 = blockIdx.x * 64;

    const uint32_t s = smem_u32(S1);
    const uint32_t aoff = ((wm * 32 + (l & 15)) * SA + (l >> 4) * 8) * 2;
    const uint32_t boff = ((wn * 32 + (l & 15)) * SA + (l >> 4) * 8) * 2;

    float accZ[2][4][4] = {}, accH[2][4][4] = {};

    g1_load(0, 0, m0, n0, tid, s); CP_COMMIT();
    g1_load(1, 1, m0, n0, tid, s); CP_COMMIT();

    int st = 0, nxt = 2;
    #pragma unroll 1
    for (int it = 0; it < 16; it++) {
        CP_WAIT1();
        __syncthreads();
        const uint32_t bS = s + st * G1_STG;
        #pragma unroll
        for (int k16 = 0; k16 < 2; k16++) {
            uint32_t a[2][4], vz[2][4], vh[2][4];
            ldm4(a[0], bS + aoff + k16 * 32);
            ldm4(a[1], bS + aoff + 16 * SA * 2 + k16 * 32);
            ldm4(vz[0], bS + G1_BZ + boff + k16 * 32);
            ldm4(vz[1], bS + G1_BZ + boff + 16 * SA * 2 + k16 * 32);
            ldm4(vh[0], bS + G1_BH + boff + k16 * 32);
            ldm4(vh[1], bS + G1_BH + boff + 16 * SA * 2 + k16 * 32);
            #pragma unroll
            for (int mt = 0; mt < 2; mt++)
                #pragma unroll
                for (int nt = 0; nt < 4; nt++) {
                    const int p = nt >> 1, q = nt & 1;
                    mma16816(accZ[mt][nt], a[mt], vz[p][q], vz[p][q + 2]);
                    mma16816(accH[mt][nt], a[mt], vh[p][q], vh[p][q + 2]);
                }
        }
        if (it + 2 < 16) g1_load(it + 2, nxt, m0, n0, tid, s);
        CP_COMMIT();
        st = (st == 2) ? 0 : st + 1;
        nxt = (nxt == 2) ? 0 : nxt + 1;
    }

    // Epilogue: a,b -> g_ab; accZ/accH overwritten in place with (a,b).
    // Value slot (mt,nt,q): row = wm*32 + mt*16 + (q>=2?8:0) + (l>>2),
    //                       col = n0 + wn*32 + nt*8 + (l&3)*2 + (q&1).
    #pragma unroll
    for (int mt = 0; mt < 2; mt++) {
        const int row = m0 + wm * 32 + mt * 16 + (l >> 2);
        #pragma unroll
        for (int nt = 0; nt < 4; nt++) {
            const int col = n0 + wn * 32 + nt * 8 + (l & 3) * 2;
            const float bz0 = __ldg(bz + col), bz1 = __ldg(bz + col + 1);
            const float bh0 = __ldg(bh + col), bh1 = __ldg(bh + col + 1);
            float z[4] = {accZ[mt][nt][0] + bz0, accZ[mt][nt][1] + bz1,
                          accZ[mt][nt][2] + bz0, accZ[mt][nt][3] + bz1};
            float h[4] = {accH[mt][nt][0] + bh0, accH[mt][nt][1] + bh1,
                          accH[mt][nt][2] + bh0, accH[mt][nt][3] + bh1};
            #pragma unroll
            for (int q = 0; q < 4; q++) {
                const float sg = 1.f / (1.f + __expf(-z[q]));
                accZ[mt][nt][q] = 1.f - sg;       // a
                accH[mt][nt][q] = sg * h[q];      // b
            }
            float4 v0 = {accZ[mt][nt][0], accH[mt][nt][0], accZ[mt][nt][1], accH[mt][nt][1]};
            float4 v1 = {accZ[mt][nt][2], accH[mt][nt][2], accZ[mt][nt][3], accH[mt][nt][3]};
            *(float4*)(g_ab + (size_t)row * HID + col) = v0;
            *(float4*)(g_ab + (size_t)(row + 8) * HID + col) = v1;
        }
    }

    // Fused chunk aggregate: butterfly-compose over lane bits 2..4 (row r0 = l>>2).
    // compose(earlier e, later t): A = At*Ae, B = At*Be + Bt.
    #pragma unroll
    for (int mask = 4; mask <= 16; mask <<= 1) {
        const bool later = (l & mask) != 0;
        #pragma unroll
        for (int mt = 0; mt < 2; mt++)
            #pragma unroll
            for (int nt = 0; nt < 4; nt++)
                #pragma unroll
                for (int q = 0; q < 4; q++) {
                    const float A = accZ[mt][nt][q], B = accH[mt][nt][q];
                    const float pA = __shfl_xor_sync(0xffffffffu, A, mask);
                    const float pB = __shfl_xor_sync(0xffffffffu, B, mask);
                    accH[mt][nt][q] = later ? fmaf(A, pB, B) : fmaf(pA, B, pB);
                    accZ[mt][nt][q] = A * pA;
                }
    }
    // In-thread compose of 4 row-blocks (order: (mt0,q), (mt0,q+2), (mt1,q), (mt1,q+2))
    if (l < 4) {
        const int chunk = blockIdx.y * 4 + wm;
        #pragma unroll
        for (int nt = 0; nt < 4; nt++)
            #pragma unroll
            for (int j = 0; j < 2; j++) {
                float A = accZ[0][nt][j], B = accH[0][nt][j];
                B = fmaf(accZ[0][nt][j + 2], B, accH[0][nt][j + 2]); A *= accZ[0][nt][j + 2];
                B = fmaf(accZ[1][nt][j],     B, accH[1][nt][j]);     A *= accZ[1][nt][j];
                B = fmaf(accZ[1][nt][j + 2], B, accH[1][nt][j + 2]); A *= accZ[1][nt][j + 2];
                g_agg[chunk * HID + n0 + wn * 32 + nt * 8 + l * 2 + j] = make_float2(A, B);
            }
    }
}

// ---------------------------------------------------------------------------
// GEMM2: out = S Wo^T + bo. BM=128 BN=64, 3-stage cp.async.
// ---------------------------------------------------------------------------
#define G2_STG 15360
#define G2_B 10240

__device__ __forceinline__ void g2_load(int chunk, int st, int m0, int n0, int tid,
                                        uint32_t s) {
    const int k0 = chunk << 5;
    const uint32_t base = s + st * G2_STG;
    #pragma unroll
    for (int j = 0; j < 2; j++) {
        const int ch = tid + j * 256, row = ch >> 2, c = ch & 3;
        cp16(base + (row * SA + c * 8) * 2,
             g_sh + (size_t)(m0 + row) * HID + k0 + c * 8);
    }
    const int row = tid >> 2, c = tid & 3;
    cp16(base + G2_B + (row * SA + c * 8) * 2,
         g_wo + (size_t)(n0 + row) * HID + k0 + c * 8);
}

__global__ __launch_bounds__(256) void gemm2_kernel(const float* __restrict__ bo,
                                                    float* __restrict__ out) {
    __shared__ __half S2[3 * G2_STG / 2];
    const int tid = threadIdx.x, wid = tid >> 5, l = tid & 31;
    const int wm = wid & 3, wn = wid >> 2;
    const int m0 = blockIdx.y * 128, n0 = blockIdx.x * 64;

    const uint32_t s = smem_u32(S2);
    const uint32_t aoff = ((wm * 32 + (l & 15)) * SA + (l >> 4) * 8) * 2;
    const uint32_t boff = ((wn * 32 + (l & 15)) * SA + (l >> 4) * 8) * 2;

    float acc[2][4][4] = {};

    g2_load(0, 0, m0, n0, tid, s); CP_COMMIT();
    g2_load(1, 1, m0, n0, tid, s); CP_COMMIT();

    int st = 0, nxt = 2;
    #pragma unroll 1
    for (int it = 0; it < 16; it++) {
        CP_WAIT1();
        __syncthreads();
        const uint32_t bS = s + st * G2_STG;
        #pragma unroll
        for (int k16 = 0; k16 < 2; k16++) {
            uint32_t a[2][4], v[2][4];
            ldm4(a[0], bS + aoff + k16 * 32);
            ldm4(a[1], bS + aoff + 16 * SA * 2 + k16 * 32);
            ldm4(v[0], bS + G2_B + boff + k16 * 32);
            ldm4(v[1], bS + G2_B + boff + 16 * SA * 2 + k16 * 32);
            #pragma unroll
            for (int mt = 0; mt < 2; mt++)
                #pragma unroll
                for (int nt = 0; nt < 4; nt++)
                    mma16816(acc[mt][nt], a[mt], v[nt >> 1][nt & 1], v[nt >> 1][(nt & 1) + 2]);
        }
        if (it + 2 < 16) g2_load(it + 2, nxt, m0, n0, tid, s);
        CP_COMMIT();
        st = (st == 2) ? 0 : st + 1;
        nxt = (nxt == 2) ? 0 : nxt + 1;
    }

    #pragma unroll
    for (int mt = 0; mt < 2; mt++) {
        const int row = m0 + wm * 32 + mt * 16 + (l >> 2);
        #pragma unroll
        for (int nt = 0; nt < 4; nt++) {
            const int col = n0 + wn * 32 + nt * 8 + (l & 3) * 2;
            const float b0 = __ldg(bo + col), b1 = __ldg(bo + col + 1);
            *(float2*)(out + (size_t)row * HID + col) =
                make_float2(acc[mt][nt][0] + b0, acc[mt][nt][1] + b1);
            *(float2*)(out + (size_t)(row + 8) * HID + col) =
                make_float2(acc[mt][nt][2] + b0, acc[mt][nt][3] + b1);
        }
    }
}

// ---------------------------------------------------------------------------
// Scan phase 2: Kogge-Stone parallel scan over NCHUNK=512 chunk aggregates.
// grid = 512 blocks (one per channel), 512 threads (one per chunk).
// ---------------------------------------------------------------------------
__global__ __launch_bounds__(512) void scan_phase2() {
    const int h = blockIdx.x, c = threadIdx.x;
    __shared__ float sA[NCHUNK], sB[NCHUNK];
    float2 ag = g_agg[c * HID + h];
    float A = ag.x, B = ag.y;
    sA[c] = A; sB[c] = B;
    __syncthreads();
    #pragma unroll
    for (int d = 1; d < NCHUNK; d <<= 1) {
        float pA = 1.f, pB = 0.f;
        if (c >= d) { pA = sA[c - d]; pB = sB[c - d]; }
        __syncthreads();
        if (c >= d) {
            B = A * pB + B;
            A = A * pA;
            sA[c] = A; sB[c] = B;
        }
        __syncthreads();
    }
    g_pref[c * HID + h] = (c == 0) ? 0.f : sB[c - 1];
}

// ---------------------------------------------------------------------------
// Scan phase 3: apply prefixes, emit states as fp16. grid (NCHUNK, 2).
// ---------------------------------------------------------------------------
__global__ __launch_bounds__(256) void scan_phase3() {
    const int c = blockIdx.x;
    const int ch = blockIdx.y * 256 + threadIdx.x;
    const float2* p = g_ab + (size_t)c * CHUNK_L * HID + ch;
    __half* q = g_sh + (size_t)c * CHUNK_L * HID + ch;
    float s = g_pref[c * HID + ch];
    #pragma unroll 8
    for (int i = 0; i < CHUNK_L; i++) {
        float2 v = p[(size_t)i * HID];
        s = v.x * s + v.y;
        q[(size_t)i * HID] = __float2half(s);
    }
}

// ---------------------------------------------------------------------------
extern "C" void kernel_launch(void* const* d_in, const int* in_sizes, int n_in,
                              void* d_out, int out_size) {
    const float* xs = (const float*)d_in[0];
    const float* Wz = (const float*)d_in[1];
    const float* bz = (const float*)d_in[2];
    const float* Wh = (const float*)d_in[3];
    const float* bh = (const float*)d_in[4];
    const float* Wo = (const float*)d_in[5];
    const float* bo = (const float*)d_in[6];
    float* out = (float*)d_out;

    cudaFuncSetAttribute(gemm1_kernel, cudaFuncAttributeMaxDynamicSharedMemorySize,
                         3 * G1_STG);

    const int ntot = NX2 + 3 * NW2;
    convert_all<<<(ntot + 255) / 256, 256>>>(xs, Wz, Wh, Wo);

    gemm1_kernel<<<dim3(HID / 64, T_LEN / 128), 256, 3 * G1_STG>>>(bz, bh);

    scan_phase2<<<HID, NCHUNK>>>();
    scan_phase3<<<dim3(NCHUNK, 2), 256>>>();

    gemm2_kernel<<<dim3(HID / 64, T_LEN / 128), 256>>>(bo, out);
}

// round 14
// speedup vs baseline: 1.0990x; 1.0990x over previous
#include <cuda_runtime.h>
#include <cuda_fp16.h>
#include <cstdint>

#define T_LEN 16384
#define HID   512
#define NCHUNK 512
#define CHUNK_L 32
#define SA 40          // smem row stride in halves (32 used + 8 pad)

// ---------------------------------------------------------------------------
// Device scratch (no runtime allocation allowed)
// ---------------------------------------------------------------------------
__device__ __half g_xh[T_LEN * HID];
__device__ __half g_wz[HID * HID], g_wh[HID * HID], g_wo[HID * HID];
__device__ __half2 g_ab[T_LEN * HID];     // (a, b) packed fp16
__device__ __half g_sh[T_LEN * HID];
__device__ float2 g_agg[NCHUNK * HID];    // (A, B) per chunk (fp32)
__device__ float g_pref[NCHUNK * HID];

// ---------------------------------------------------------------------------
// PTX helpers (sm_80-era: valid under compute_103 virtual arch)
// ---------------------------------------------------------------------------
__device__ __forceinline__ uint32_t smem_u32(const void* p) {
    uint32_t a;
    asm("{ .reg .u64 t; cvta.to.shared.u64 t, %1; cvt.u32.u64 %0, t; }" : "=r"(a) : "l"(p));
    return a;
}

__device__ __forceinline__ void cp16(uint32_t dst, const void* src) {
    asm volatile("cp.async.ca.shared.global [%0], [%1], 16;" :: "r"(dst), "l"(src));
}
#define CP_COMMIT() asm volatile("cp.async.commit_group;" ::: "memory")
#define CP_WAIT1()  asm volatile("cp.async.wait_group 1;" ::: "memory")

__device__ __forceinline__ void ldm4(uint32_t* r, uint32_t addr) {
    asm volatile("ldmatrix.sync.aligned.m8n8.x4.shared.b16 {%0,%1,%2,%3}, [%4];"
                 : "=r"(r[0]), "=r"(r[1]), "=r"(r[2]), "=r"(r[3]) : "r"(addr));
}

__device__ __forceinline__ void mma16816(float* d, const uint32_t* a, uint32_t b0, uint32_t b1) {
    asm volatile(
        "mma.sync.aligned.m16n8k16.row.col.f32.f16.f16.f32 "
        "{%0,%1,%2,%3}, {%4,%5,%6,%7}, {%8,%9}, {%0,%1,%2,%3};"
        : "+f"(d[0]), "+f"(d[1]), "+f"(d[2]), "+f"(d[3])
        : "r"(a[0]), "r"(a[1]), "r"(a[2]), "r"(a[3]), "r"(b0), "r"(b1));
}

// ---------------------------------------------------------------------------
// Fused fp32 -> fp16 converter: X then Wz, Wh, Wo, one launch.
// ---------------------------------------------------------------------------
#define NX2 (T_LEN * HID / 2)
#define NW2 (HID * HID / 2)

__global__ __launch_bounds__(256) void convert_all(const float* __restrict__ xs,
                                                   const float* __restrict__ Wz,
                                                   const float* __restrict__ Wh,
                                                   const float* __restrict__ Wo) {
    int i = blockIdx.x * 256 + threadIdx.x;
    const float* src;
    __half* dst;
    int j;
    if (i < NX2)                 { src = xs; dst = g_xh; j = i; }
    else if (i < NX2 + NW2)      { src = Wz; dst = g_wz; j = i - NX2; }
    else if (i < NX2 + 2 * NW2)  { src = Wh; dst = g_wh; j = i - NX2 - NW2; }
    else if (i < NX2 + 3 * NW2)  { src = Wo; dst = g_wo; j = i - NX2 - 2 * NW2; }
    else return;
    float2 x = *(const float2*)(src + j * 2);
    *(__half2*)(dst + j * 2) = __halves2half2(__float2half(x.x), __float2half(x.y));
}

// ---------------------------------------------------------------------------
// GEMM1: Z = X Wz^T + bz, Hc = X Wh^T + bh -> g_ab = half2(1-sig(Z), sig(Z)*Hc)
// BM=128 BN=64 BK=32, 16 chunks, 3-stage cp.async, one sync per iteration.
// ---------------------------------------------------------------------------
#define G1_STG 20480
#define G1_BZ 10240
#define G1_BH 15360

__device__ __forceinline__ void g1_load(int chunk, int st, int m0, int n0, int tid,
                                        uint32_t s) {
    const int k0 = chunk << 5;
    const uint32_t base = s + st * G1_STG;
    #pragma unroll
    for (int j = 0; j < 2; j++) {
        const int ch = tid + j * 256, row = ch >> 2, c = ch & 3;
        cp16(base + (row * SA + c * 8) * 2,
             g_xh + (size_t)(m0 + row) * HID + k0 + c * 8);
    }
    const int row = tid >> 2, c = tid & 3;
    const uint32_t off = (row * SA + c * 8) * 2;
    const size_t gsrc = (size_t)(n0 + row) * HID + k0 + c * 8;
    cp16(base + G1_BZ + off, g_wz + gsrc);
    cp16(base + G1_BH + off, g_wh + gsrc);
}

__global__ __launch_bounds__(256) void gemm1_kernel(const float* __restrict__ bz,
                                                    const float* __restrict__ bh) {
    extern __shared__ __half S1[];
    const int tid = threadIdx.x, wid = tid >> 5, l = tid & 31;
    const int wm = wid & 3, wn = wid >> 2;
    const int m0 = blockIdx.y * 128, n0 = blockIdx.x * 64;

    const uint32_t s = smem_u32(S1);
    const uint32_t aoff = ((wm * 32 + (l & 15)) * SA + (l >> 4) * 8) * 2;
    const uint32_t boff = ((wn * 32 + (l & 15)) * SA + (l >> 4) * 8) * 2;

    float accZ[2][4][4] = {}, accH[2][4][4] = {};

    g1_load(0, 0, m0, n0, tid, s); CP_COMMIT();
    g1_load(1, 1, m0, n0, tid, s); CP_COMMIT();

    int st = 0, nxt = 2;
    #pragma unroll 1
    for (int it = 0; it < 16; it++) {
        CP_WAIT1();
        __syncthreads();
        const uint32_t bS = s + st * G1_STG;
        #pragma unroll
        for (int k16 = 0; k16 < 2; k16++) {
            uint32_t a[2][4], vz[2][4], vh[2][4];
            ldm4(a[0], bS + aoff + k16 * 32);
            ldm4(a[1], bS + aoff + 16 * SA * 2 + k16 * 32);
            ldm4(vz[0], bS + G1_BZ + boff + k16 * 32);
            ldm4(vz[1], bS + G1_BZ + boff + 16 * SA * 2 + k16 * 32);
            ldm4(vh[0], bS + G1_BH + boff + k16 * 32);
            ldm4(vh[1], bS + G1_BH + boff + 16 * SA * 2 + k16 * 32);
            #pragma unroll
            for (int mt = 0; mt < 2; mt++)
                #pragma unroll
                for (int nt = 0; nt < 4; nt++) {
                    const int p = nt >> 1, q = nt & 1;
                    mma16816(accZ[mt][nt], a[mt], vz[p][q], vz[p][q + 2]);
                    mma16816(accH[mt][nt], a[mt], vh[p][q], vh[p][q + 2]);
                }
        }
        if (it + 2 < 16) g1_load(it + 2, nxt, m0, n0, tid, s);
        CP_COMMIT();
        st = (st == 2) ? 0 : st + 1;
        nxt = (nxt == 2) ? 0 : nxt + 1;
    }

    // epilogue: a = 1 - sigmoid(z), b = sigmoid(z) * h -> packed half2
    #pragma unroll
    for (int mt = 0; mt < 2; mt++) {
        const int row = m0 + wm * 32 + mt * 16 + (l >> 2);
        #pragma unroll
        for (int nt = 0; nt < 4; nt++) {
            const int col = n0 + wn * 32 + nt * 8 + (l & 3) * 2;
            const float bz0 = __ldg(bz + col), bz1 = __ldg(bz + col + 1);
            const float bh0 = __ldg(bh + col), bh1 = __ldg(bh + col + 1);
            float z[4] = {accZ[mt][nt][0] + bz0, accZ[mt][nt][1] + bz1,
                          accZ[mt][nt][2] + bz0, accZ[mt][nt][3] + bz1};
            float h[4] = {accH[mt][nt][0] + bh0, accH[mt][nt][1] + bh1,
                          accH[mt][nt][2] + bh0, accH[mt][nt][3] + bh1};
            float sg[4];
            #pragma unroll
            for (int q = 0; q < 4; q++) sg[q] = 1.f / (1.f + __expf(-z[q]));
            __half2 p00 = __floats2half2_rn(1.f - sg[0], sg[0] * h[0]);
            __half2 p01 = __floats2half2_rn(1.f - sg[1], sg[1] * h[1]);
            __half2 p10 = __floats2half2_rn(1.f - sg[2], sg[2] * h[2]);
            __half2 p11 = __floats2half2_rn(1.f - sg[3], sg[3] * h[3]);
            uint2 v0 = {*(uint32_t*)&p00, *(uint32_t*)&p01};
            uint2 v1 = {*(uint32_t*)&p10, *(uint32_t*)&p11};
            *(uint2*)(g_ab + (size_t)row * HID + col) = v0;
            *(uint2*)(g_ab + (size_t)(row + 8) * HID + col) = v1;
        }
    }
}

// ---------------------------------------------------------------------------
// GEMM2: out = S Wo^T + bo. BM=128 BN=64, 3-stage cp.async.
// ---------------------------------------------------------------------------
#define G2_STG 15360
#define G2_B 10240

__device__ __forceinline__ void g2_load(int chunk, int st, int m0, int n0, int tid,
                                        uint32_t s) {
    const int k0 = chunk << 5;
    const uint32_t base = s + st * G2_STG;
    #pragma unroll
    for (int j = 0; j < 2; j++) {
        const int ch = tid + j * 256, row = ch >> 2, c = ch & 3;
        cp16(base + (row * SA + c * 8) * 2,
             g_sh + (size_t)(m0 + row) * HID + k0 + c * 8);
    }
    const int row = tid >> 2, c = tid & 3;
    cp16(base + G2_B + (row * SA + c * 8) * 2,
         g_wo + (size_t)(n0 + row) * HID + k0 + c * 8);
}

__global__ __launch_bounds__(256) void gemm2_kernel(const float* __restrict__ bo,
                                                    float* __restrict__ out) {
    __shared__ __half S2[3 * G2_STG / 2];
    const int tid = threadIdx.x, wid = tid >> 5, l = tid & 31;
    const int wm = wid & 3, wn = wid >> 2;
    const int m0 = blockIdx.y * 128, n0 = blockIdx.x * 64;

    const uint32_t s = smem_u32(S2);
    const uint32_t aoff = ((wm * 32 + (l & 15)) * SA + (l >> 4) * 8) * 2;
    const uint32_t boff = ((wn * 32 + (l & 15)) * SA + (l >> 4) * 8) * 2;

    float acc[2][4][4] = {};

    g2_load(0, 0, m0, n0, tid, s); CP_COMMIT();
    g2_load(1, 1, m0, n0, tid, s); CP_COMMIT();

    int st = 0, nxt = 2;
    #pragma unroll 1
    for (int it = 0; it < 16; it++) {
        CP_WAIT1();
        __syncthreads();
        const uint32_t bS = s + st * G2_STG;
        #pragma unroll
        for (int k16 = 0; k16 < 2; k16++) {
            uint32_t a[2][4], v[2][4];
            ldm4(a[0], bS + aoff + k16 * 32);
            ldm4(a[1], bS + aoff + 16 * SA * 2 + k16 * 32);
            ldm4(v[0], bS + G2_B + boff + k16 * 32);
            ldm4(v[1], bS + G2_B + boff + 16 * SA * 2 + k16 * 32);
            #pragma unroll
            for (int mt = 0; mt < 2; mt++)
                #pragma unroll
                for (int nt = 0; nt < 4; nt++)
                    mma16816(acc[mt][nt], a[mt], v[nt >> 1][nt & 1], v[nt >> 1][(nt & 1) + 2]);
        }
        if (it + 2 < 16) g2_load(it + 2, nxt, m0, n0, tid, s);
        CP_COMMIT();
        st = (st == 2) ? 0 : st + 1;
        nxt = (nxt == 2) ? 0 : nxt + 1;
    }

    #pragma unroll
    for (int mt = 0; mt < 2; mt++) {
        const int row = m0 + wm * 32 + mt * 16 + (l >> 2);
        #pragma unroll
        for (int nt = 0; nt < 4; nt++) {
            const int col = n0 + wn * 32 + nt * 8 + (l & 3) * 2;
            const float b0 = __ldg(bo + col), b1 = __ldg(bo + col + 1);
            *(float2*)(out + (size_t)row * HID + col) =
                make_float2(acc[mt][nt][0] + b0, acc[mt][nt][1] + b1);
            *(float2*)(out + (size_t)(row + 8) * HID + col) =
                make_float2(acc[mt][nt][2] + b0, acc[mt][nt][3] + b1);
        }
    }
}

// ---------------------------------------------------------------------------
// Scan phase 1: per-chunk aggregates (fp32 math on half2 input).
// grid (NCHUNK, 2), 256 threads, 1 channel/thread.
// ---------------------------------------------------------------------------
__global__ __launch_bounds__(256) void scan_phase1() {
    const int c = blockIdx.x;
    const int ch = blockIdx.y * 256 + threadIdx.x;
    const __half2* p = g_ab + (size_t)c * CHUNK_L * HID + ch;
    float A = 1.f, B = 0.f;
    #pragma unroll 8
    for (int i = 0; i < CHUNK_L; i++) {
        float2 v = __half22float2(p[(size_t)i * HID]);
        A = v.x * A;
        B = v.x * B + v.y;
    }
    g_agg[c * HID + ch] = make_float2(A, B);
}

// ---------------------------------------------------------------------------
// Scan phase 2: Kogge-Stone parallel scan over NCHUNK=512 chunk aggregates.
// grid = 512 blocks (one per channel), 512 threads (one per chunk).
// ---------------------------------------------------------------------------
__global__ __launch_bounds__(512) void scan_phase2() {
    const int h = blockIdx.x, c = threadIdx.x;
    __shared__ float sA[NCHUNK], sB[NCHUNK];
    float2 ag = g_agg[c * HID + h];
    float A = ag.x, B = ag.y;
    sA[c] = A; sB[c] = B;
    __syncthreads();
    #pragma unroll
    for (int d = 1; d < NCHUNK; d <<= 1) {
        float pA = 1.f, pB = 0.f;
        if (c >= d) { pA = sA[c - d]; pB = sB[c - d]; }
        __syncthreads();
        if (c >= d) {
            B = A * pB + B;
            A = A * pA;
            sA[c] = A; sB[c] = B;
        }
        __syncthreads();
    }
    g_pref[c * HID + h] = (c == 0) ? 0.f : sB[c - 1];
}

// ---------------------------------------------------------------------------
// Scan phase 3: apply prefixes, emit states as fp16. grid (NCHUNK, 2).
// ---------------------------------------------------------------------------
__global__ __launch_bounds__(256) void scan_phase3() {
    const int c = blockIdx.x;
    const int ch = blockIdx.y * 256 + threadIdx.x;
    const __half2* p = g_ab + (size_t)c * CHUNK_L * HID + ch;
    __half* q = g_sh + (size_t)c * CHUNK_L * HID + ch;
    float s = g_pref[c * HID + ch];
    #pragma unroll 8
    for (int i = 0; i < CHUNK_L; i++) {
        float2 v = __half22float2(p[(size_t)i * HID]);
        s = v.x * s + v.y;
        q[(size_t)i * HID] = __float2half(s);
    }
}

// ---------------------------------------------------------------------------
extern "C" void kernel_launch(void* const* d_in, const int* in_sizes, int n_in,
                              void* d_out, int out_size) {
    const float* xs = (const float*)d_in[0];
    const float* Wz = (const float*)d_in[1];
    const float* bz = (const float*)d_in[2];
    const float* Wh = (const float*)d_in[3];
    const float* bh = (const float*)d_in[4];
    const float* Wo = (const float*)d_in[5];
    const float* bo = (const float*)d_in[6];
    float* out = (float*)d_out;

    cudaFuncSetAttribute(gemm1_kernel, cudaFuncAttributeMaxDynamicSharedMemorySize,
                         3 * G1_STG);

    const int ntot = NX2 + 3 * NW2;
    convert_all<<<(ntot + 255) / 256, 256>>>(xs, Wz, Wh, Wo);

    gemm1_kernel<<<dim3(HID / 64, T_LEN / 128), 256, 3 * G1_STG>>>(bz, bh);

    scan_phase1<<<dim3(NCHUNK, 2), 256>>>();
    scan_phase2<<<HID, NCHUNK>>>();
    scan_phase3<<<dim3(NCHUNK, 2), 256>>>();

    gemm2_kernel<<<dim3(HID / 64, T_LEN / 128), 256>>>(bo, out);
}

// round 15
// speedup vs baseline: 1.1131x; 1.0128x over previous
#include <cuda_runtime.h>
#include <cuda_fp16.h>
#include <cstdint>

#define T_LEN 16384
#define HID   512
#define NCHUNK 512
#define CHUNK_L 32
#define SA 40          // smem row stride in halves (32 used + 8 pad)

// ---------------------------------------------------------------------------
// Device scratch (no runtime allocation allowed)
// ---------------------------------------------------------------------------
__device__ __half g_xh[T_LEN * HID];
__device__ __half g_wz[HID * HID], g_wh[HID * HID], g_wo[HID * HID];
__device__ __half2 g_ab[T_LEN * HID];     // (a, b) packed fp16
__device__ __half g_sh[T_LEN * HID];
__device__ float2 g_agg[NCHUNK * HID];    // (A, B) per chunk (fp32)
__device__ float g_pref[NCHUNK * HID];

// ---------------------------------------------------------------------------
// PTX helpers (sm_80-era: valid under compute_103 virtual arch)
// ---------------------------------------------------------------------------
__device__ __forceinline__ uint32_t smem_u32(const void* p) {
    uint32_t a;
    asm("{ .reg .u64 t; cvta.to.shared.u64 t, %1; cvt.u32.u64 %0, t; }" : "=r"(a) : "l"(p));
    return a;
}

__device__ __forceinline__ void cp16(uint32_t dst, const void* src) {
    asm volatile("cp.async.ca.shared.global [%0], [%1], 16;" :: "r"(dst), "l"(src));
}
#define CP_COMMIT() asm volatile("cp.async.commit_group;" ::: "memory")
#define CP_WAIT1()  asm volatile("cp.async.wait_group 1;" ::: "memory")

__device__ __forceinline__ void ldm4(uint32_t* r, uint32_t addr) {
    asm volatile("ldmatrix.sync.aligned.m8n8.x4.shared.b16 {%0,%1,%2,%3}, [%4];"
                 : "=r"(r[0]), "=r"(r[1]), "=r"(r[2]), "=r"(r[3]) : "r"(addr));
}

__device__ __forceinline__ void mma16816(float* d, const uint32_t* a, uint32_t b0, uint32_t b1) {
    asm volatile(
        "mma.sync.aligned.m16n8k16.row.col.f32.f16.f16.f32 "
        "{%0,%1,%2,%3}, {%4,%5,%6,%7}, {%8,%9}, {%0,%1,%2,%3};"
        : "+f"(d[0]), "+f"(d[1]), "+f"(d[2]), "+f"(d[3])
        : "r"(a[0]), "r"(a[1]), "r"(a[2]), "r"(a[3]), "r"(b0), "r"(b1));
}

// ---------------------------------------------------------------------------
// Fused fp32 -> fp16 converter: X then Wz, Wh, Wo, one launch.
// ---------------------------------------------------------------------------
#define NX2 (T_LEN * HID / 2)
#define NW2 (HID * HID / 2)

__global__ __launch_bounds__(256) void convert_all(const float* __restrict__ xs,
                                                   const float* __restrict__ Wz,
                                                   const float* __restrict__ Wh,
                                                   const float* __restrict__ Wo) {
    int i = blockIdx.x * 256 + threadIdx.x;
    const float* src;
    __half* dst;
    int j;
    if (i < NX2)                 { src = xs; dst = g_xh; j = i; }
    else if (i < NX2 + NW2)      { src = Wz; dst = g_wz; j = i - NX2; }
    else if (i < NX2 + 2 * NW2)  { src = Wh; dst = g_wh; j = i - NX2 - NW2; }
    else if (i < NX2 + 3 * NW2)  { src = Wo; dst = g_wo; j = i - NX2 - 2 * NW2; }
    else return;
    float2 x = *(const float2*)(src + j * 2);
    *(__half2*)(dst + j * 2) = __halves2half2(__float2half(x.x), __float2half(x.y));
}

// ---------------------------------------------------------------------------
// GEMM1: Z = X Wz^T + bz, Hc = X Wh^T + bh -> g_ab = half2(1-sig(Z), sig(Z)*Hc)
// BM=128 BN=64 BK=32, 16 chunks, 3-stage cp.async, one sync per iteration.
// ---------------------------------------------------------------------------
#define G1_STG 20480
#define G1_BZ 10240
#define G1_BH 15360

__device__ __forceinline__ void g1_load(int chunk, int st, int m0, int n0, int tid,
                                        uint32_t s) {
    const int k0 = chunk << 5;
    const uint32_t base = s + st * G1_STG;
    #pragma unroll
    for (int j = 0; j < 2; j++) {
        const int ch = tid + j * 256, row = ch >> 2, c = ch & 3;
        cp16(base + (row * SA + c * 8) * 2,
             g_xh + (size_t)(m0 + row) * HID + k0 + c * 8);
    }
    const int row = tid >> 2, c = tid & 3;
    const uint32_t off = (row * SA + c * 8) * 2;
    const size_t gsrc = (size_t)(n0 + row) * HID + k0 + c * 8;
    cp16(base + G1_BZ + off, g_wz + gsrc);
    cp16(base + G1_BH + off, g_wh + gsrc);
}

__global__ __launch_bounds__(256) void gemm1_kernel(const float* __restrict__ bz,
                                                    const float* __restrict__ bh) {
    extern __shared__ __half S1[];
    const int tid = threadIdx.x, wid = tid >> 5, l = tid & 31;
    const int wm = wid & 3, wn = wid >> 2;
    const int m0 = blockIdx.y * 128, n0 = blockIdx.x * 64;

    const uint32_t s = smem_u32(S1);
    const uint32_t aoff = ((wm * 32 + (l & 15)) * SA + (l >> 4) * 8) * 2;
    const uint32_t boff = ((wn * 32 + (l & 15)) * SA + (l >> 4) * 8) * 2;

    float accZ[2][4][4] = {}, accH[2][4][4] = {};

    g1_load(0, 0, m0, n0, tid, s); CP_COMMIT();
    g1_load(1, 1, m0, n0, tid, s); CP_COMMIT();

    int st = 0, nxt = 2;
    #pragma unroll 1
    for (int it = 0; it < 16; it++) {
        CP_WAIT1();
        __syncthreads();
        const uint32_t bS = s + st * G1_STG;
        #pragma unroll
        for (int k16 = 0; k16 < 2; k16++) {
            uint32_t a[2][4], vz[2][4], vh[2][4];
            ldm4(a[0], bS + aoff + k16 * 32);
            ldm4(a[1], bS + aoff + 16 * SA * 2 + k16 * 32);
            ldm4(vz[0], bS + G1_BZ + boff + k16 * 32);
            ldm4(vz[1], bS + G1_BZ + boff + 16 * SA * 2 + k16 * 32);
            ldm4(vh[0], bS + G1_BH + boff + k16 * 32);
            ldm4(vh[1], bS + G1_BH + boff + 16 * SA * 2 + k16 * 32);
            #pragma unroll
            for (int mt = 0; mt < 2; mt++)
                #pragma unroll
                for (int nt = 0; nt < 4; nt++) {
                    const int p = nt >> 1, q = nt & 1;
                    mma16816(accZ[mt][nt], a[mt], vz[p][q], vz[p][q + 2]);
                    mma16816(accH[mt][nt], a[mt], vh[p][q], vh[p][q + 2]);
                }
        }
        if (it + 2 < 16) g1_load(it + 2, nxt, m0, n0, tid, s);
        CP_COMMIT();
        st = (st == 2) ? 0 : st + 1;
        nxt = (nxt == 2) ? 0 : nxt + 1;
    }

    // epilogue: a = 1 - sigmoid(z), b = sigmoid(z) * h -> packed half2
    #pragma unroll
    for (int mt = 0; mt < 2; mt++) {
        const int row = m0 + wm * 32 + mt * 16 + (l >> 2);
        #pragma unroll
        for (int nt = 0; nt < 4; nt++) {
            const int col = n0 + wn * 32 + nt * 8 + (l & 3) * 2;
            const float bz0 = __ldg(bz + col), bz1 = __ldg(bz + col + 1);
            const float bh0 = __ldg(bh + col), bh1 = __ldg(bh + col + 1);
            float z[4] = {accZ[mt][nt][0] + bz0, accZ[mt][nt][1] + bz1,
                          accZ[mt][nt][2] + bz0, accZ[mt][nt][3] + bz1};
            float h[4] = {accH[mt][nt][0] + bh0, accH[mt][nt][1] + bh1,
                          accH[mt][nt][2] + bh0, accH[mt][nt][3] + bh1};
            float sg[4];
            #pragma unroll
            for (int q = 0; q < 4; q++) sg[q] = 1.f / (1.f + __expf(-z[q]));
            __half2 p00 = __floats2half2_rn(1.f - sg[0], sg[0] * h[0]);
            __half2 p01 = __floats2half2_rn(1.f - sg[1], sg[1] * h[1]);
            __half2 p10 = __floats2half2_rn(1.f - sg[2], sg[2] * h[2]);
            __half2 p11 = __floats2half2_rn(1.f - sg[3], sg[3] * h[3]);
            uint2 v0 = {*(uint32_t*)&p00, *(uint32_t*)&p01};
            uint2 v1 = {*(uint32_t*)&p10, *(uint32_t*)&p11};
            *(uint2*)(g_ab + (size_t)row * HID + col) = v0;
            *(uint2*)(g_ab + (size_t)(row + 8) * HID + col) = v1;
        }
    }
}

// ---------------------------------------------------------------------------
// GEMM2: out = S Wo^T + bo.
// BM=128 BN=128, 256 threads, warp tile 64x32 (2x4 warp grid), 3-stage.
// smem: 3 x (A 10240 + B 10240) = 61440B dynamic.
// ---------------------------------------------------------------------------
#define G2_STG 20480
#define G2_B 10240

__device__ __forceinline__ void g2_load(int chunk, int st, int m0, int n0, int tid,
                                        uint32_t s) {
    const int k0 = chunk << 5;
    const uint32_t base = s + st * G2_STG;
    #pragma unroll
    for (int j = 0; j < 2; j++) {
        const int ch = tid + j * 256, row = ch >> 2, c = ch & 3;
        const uint32_t off = (row * SA + c * 8) * 2;
        cp16(base + off, g_sh + (size_t)(m0 + row) * HID + k0 + c * 8);
        cp16(base + G2_B + off, g_wo + (size_t)(n0 + row) * HID + k0 + c * 8);
    }
}

__global__ __launch_bounds__(256, 2) void gemm2_kernel(const float* __restrict__ bo,
                                                       float* __restrict__ out) {
    extern __shared__ __half S2[];
    const int tid = threadIdx.x, wid = tid >> 5, l = tid & 31;
    const int wm = wid & 1, wn = wid >> 1;   // 2 m-rows x 4 n-cols of warps
    const int m0 = blockIdx.y * 128, n0 = blockIdx.x * 128;

    const uint32_t s = smem_u32(S2);
    const uint32_t aoff = ((wm * 64 + (l & 15)) * SA + (l >> 4) * 8) * 2;
    const uint32_t boff = ((wn * 32 + (l & 15)) * SA + (l >> 4) * 8) * 2;

    float acc[4][4][4] = {};

    g2_load(0, 0, m0, n0, tid, s); CP_COMMIT();
    g2_load(1, 1, m0, n0, tid, s); CP_COMMIT();

    int st = 0, nxt = 2;
    #pragma unroll 1
    for (int it = 0; it < 16; it++) {
        CP_WAIT1();
        __syncthreads();
        const uint32_t bS = s + st * G2_STG;
        #pragma unroll
        for (int k16 = 0; k16 < 2; k16++) {
            uint32_t a[4][4], v[2][4];
            #pragma unroll
            for (int mi = 0; mi < 4; mi++)
                ldm4(a[mi], bS + aoff + mi * 16 * SA * 2 + k16 * 32);
            ldm4(v[0], bS + G2_B + boff + k16 * 32);
            ldm4(v[1], bS + G2_B + boff + 16 * SA * 2 + k16 * 32);
            #pragma unroll
            for (int mi = 0; mi < 4; mi++)
                #pragma unroll
                for (int nj = 0; nj < 4; nj++)
                    mma16816(acc[mi][nj], a[mi], v[nj >> 1][nj & 1], v[nj >> 1][(nj & 1) + 2]);
        }
        if (it + 2 < 16) g2_load(it + 2, nxt, m0, n0, tid, s);
        CP_COMMIT();
        st = (st == 2) ? 0 : st + 1;
        nxt = (nxt == 2) ? 0 : nxt + 1;
    }

    #pragma unroll
    for (int mi = 0; mi < 4; mi++) {
        const int row = m0 + wm * 64 + mi * 16 + (l >> 2);
        #pragma unroll
        for (int nj = 0; nj < 4; nj++) {
            const int col = n0 + wn * 32 + nj * 8 + (l & 3) * 2;
            const float b0 = __ldg(bo + col), b1 = __ldg(bo + col + 1);
            *(float2*)(out + (size_t)row * HID + col) =
                make_float2(acc[mi][nj][0] + b0, acc[mi][nj][1] + b1);
            *(float2*)(out + (size_t)(row + 8) * HID + col) =
                make_float2(acc[mi][nj][2] + b0, acc[mi][nj][3] + b1);
        }
    }
}

// ---------------------------------------------------------------------------
// Scan phase 1: per-chunk aggregates (fp32 math on half2 input).
// ---------------------------------------------------------------------------
__global__ __launch_bounds__(256) void scan_phase1() {
    const int c = blockIdx.x;
    const int ch = blockIdx.y * 256 + threadIdx.x;
    const __half2* p = g_ab + (size_t)c * CHUNK_L * HID + ch;
    float A = 1.f, B = 0.f;
    #pragma unroll 8
    for (int i = 0; i < CHUNK_L; i++) {
        float2 v = __half22float2(p[(size_t)i * HID]);
        A = v.x * A;
        B = v.x * B + v.y;
    }
    g_agg[c * HID + ch] = make_float2(A, B);
}

// ---------------------------------------------------------------------------
// Scan phase 2: Kogge-Stone parallel scan over NCHUNK=512 chunk aggregates.
// ---------------------------------------------------------------------------
__global__ __launch_bounds__(512) void scan_phase2() {
    const int h = blockIdx.x, c = threadIdx.x;
    __shared__ float sA[NCHUNK], sB[NCHUNK];
    float2 ag = g_agg[c * HID + h];
    float A = ag.x, B = ag.y;
    sA[c] = A; sB[c] = B;
    __syncthreads();
    #pragma unroll
    for (int d = 1; d < NCHUNK; d <<= 1) {
        float pA = 1.f, pB = 0.f;
        if (c >= d) { pA = sA[c - d]; pB = sB[c - d]; }
        __syncthreads();
        if (c >= d) {
            B = A * pB + B;
            A = A * pA;
            sA[c] = A; sB[c] = B;
        }
        __syncthreads();
    }
    g_pref[c * HID + h] = (c == 0) ? 0.f : sB[c - 1];
}

// ---------------------------------------------------------------------------
// Scan phase 3: apply prefixes, emit states as fp16. grid (NCHUNK, 2).
// ---------------------------------------------------------------------------
__global__ __launch_bounds__(256) void scan_phase3() {
    const int c = blockIdx.x;
    const int ch = blockIdx.y * 256 + threadIdx.x;
    const __half2* p = g_ab + (size_t)c * CHUNK_L * HID + ch;
    __half* q = g_sh + (size_t)c * CHUNK_L * HID + ch;
    float s = g_pref[c * HID + ch];
    #pragma unroll 8
    for (int i = 0; i < CHUNK_L; i++) {
        float2 v = __half22float2(p[(size_t)i * HID]);
        s = v.x * s + v.y;
        q[(size_t)i * HID] = __float2half(s);
    }
}

// ---------------------------------------------------------------------------
extern "C" void kernel_launch(void* const* d_in, const int* in_sizes, int n_in,
                              void* d_out, int out_size) {
    const float* xs = (const float*)d_in[0];
    const float* Wz = (const float*)d_in[1];
    const float* bz = (const float*)d_in[2];
    const float* Wh = (const float*)d_in[3];
    const float* bh = (const float*)d_in[4];
    const float* Wo = (const float*)d_in[5];
    const float* bo = (const float*)d_in[6];
    float* out = (float*)d_out;

    cudaFuncSetAttribute(gemm1_kernel, cudaFuncAttributeMaxDynamicSharedMemorySize,
                         3 * G1_STG);
    cudaFuncSetAttribute(gemm2_kernel, cudaFuncAttributeMaxDynamicSharedMemorySize,
                         3 * G2_STG);

    const int ntot = NX2 + 3 * NW2;
    convert_all<<<(ntot + 255) / 256, 256>>>(xs, Wz, Wh, Wo);

    gemm1_kernel<<<dim3(HID / 64, T_LEN / 128), 256, 3 * G1_STG>>>(bz, bh);

    scan_phase1<<<dim3(NCHUNK, 2), 256>>>();
    scan_phase2<<<HID, NCHUNK>>>();
    scan_phase3<<<dim3(NCHUNK, 2), 256>>>();

    gemm2_kernel<<<dim3(HID / 128, T_LEN / 128), 256, 3 * G2_STG>>>(bo, out);
}